// round 17
// baseline (speedup 1.0000x reference)
#include <cuda_runtime.h>

#define NXc 64
#define NYc 64
#define NSPOTS 64
#define Pc 6
#define TPB 256
#define RS  70                   // row stride: 70 mod 32 = 6 -> bank = (base+p)%32, conflict-free
#define IMG_ROWS 70              // 64 real + 6 pad rows (sentinel target for invalid spots)
#define IMG_FLOATS (IMG_ROWS * RS)

__device__ __forceinline__ void reds_add_f32(unsigned smem_addr, float v)
{
    asm volatile("red.shared.add.f32 [%0], %1;" :: "r"(smem_addr), "f"(v) : "memory");
}

// Abramowitz-Stegun 7.1.26: |err| <= 1.5e-7 abs, branch-free
__device__ __forceinline__ float erf_as(float x)
{
    const float ax = fabsf(x);
    const float t  = __fdividef(1.0f, fmaf(0.3275911f, ax, 1.0f));
    float p = fmaf(1.061405429f, t, -1.453152027f);
    p = fmaf(p, t,  1.421413741f);
    p = fmaf(p, t, -0.284496736f);
    p = fmaf(p, t,  0.254829592f);
    p *= t;
    const float e = __expf(-ax * ax);
    const float r = fmaf(-p, e, 1.0f);
    return copysignf(r, x);
}

__global__ __launch_bounds__(TPB) void spot_render_kernel(
    const float* __restrict__ z, float* __restrict__ out)
{
    __shared__ float img[IMG_FLOATS];    // 19.6 KB; pad region never zeroed/read
    __shared__ float slx[NSPOTS * Pc];   // 500 * dx * valid
    __shared__ float sly[NSPOTS * Pc];   // 0.5 * dy * valid
    __shared__ int   sbase[NSPOTS];      // RS*r0 + c0, or RS*64 sentinel if invalid

    const int b    = blockIdx.x;
    const int tid  = threadIdx.x;
    const int lane = tid & 31;
    const int w    = tid >> 5;

    const float inv_alpha = 1.0f / (1.41421356237f * 0.92f);

    // ---- balanced prologue, ONE sync ----
    {
        // zero only the 64 used columns of the 64 real rows (pad never read)
        const int r  = tid >> 2;             // 0..63
        const int cg = tid & 3;
        float2* row2 = reinterpret_cast<float2*>(&img[RS * r]);  // 70r even -> 8B aligned
        #pragma unroll
        for (int k = 0; k < 8; k++)
            row2[cg * 8 + k] = make_float2(0.f, 0.f);
    }
    {
        const int it = tid & 127;                // (s, d) item
        const int h  = tid >> 7;                 // half: j = 3h .. 3h+3
        const int s  = it & 63;
        const int d  = it >> 6;                  // 0 = x, 1 = y
        const float* zrow = z + (size_t)b * (2 * NSPOTS);
        const float x0 = __ldg(zrow + s);
        const float y0 = __ldg(zrow + NSPOTS + s);
        const int px = __float2int_rn(x0) - 3;   // round-half-even == jnp.round
        const int py = __float2int_rn(y0) - 3;
        const bool valid = (px >= 0) & (px < NXc - Pc) & (py >= 0) & (py < NYc - Pc);

        if ((d | h) == 0)
            sbase[s] = valid ? (RS * px + py) : (RS * 64);   // sentinel: pad rows

        const float t0 = d ? (y0 - (float)py) : (x0 - (float)px);
        const float scale = (d ? 0.5f : 500.0f) * (valid ? 1.0f : 0.0f);
        const int jb = h * 3;
        const float e0 = erf_as(((float)(jb + 0) - 0.5f - t0) * inv_alpha);
        const float e1 = erf_as(((float)(jb + 1) - 0.5f - t0) * inv_alpha);
        const float e2 = erf_as(((float)(jb + 2) - 0.5f - t0) * inv_alpha);
        const float e3 = erf_as(((float)(jb + 3) - 0.5f - t0) * inv_alpha);
        float* dst = (d ? sly : slx) + s * Pc + jb;
        dst[0] = (e1 - e0) * scale;
        dst[1] = (e2 - e1) * scale;
        dst[2] = (e3 - e2) * scale;
    }
    __syncthreads();

    // ---- phase C: branchless scatter, 9 no-return atomics per warp ----
    // pixel (ix,iy): smem offset = base + RS*ix + iy = base + p + 64*ix  (p = 6ix+iy)
    unsigned img_u32;
    {
        unsigned u;
        asm("{ .reg .u64 t; cvta.to.shared.u64 t, %1; cvt.u32.u64 %0, t; }"
            : "=r"(u) : "l"(img));
        img_u32 = u;
    }
    const int p    = lane;
    const int ix   = (p * 171) >> 10;            // p/6 for p <= 35
    const int iy   = p - ix * Pc;
    const int loff = p + 64 * ix;                // = RS*ix + iy, per-lane constant
    #pragma unroll
    for (int k = 0; k < 8; k++) {
        const int s    = w * 8 + k;
        const int base = sbase[s];               // broadcast
        const float v  = slx[s * Pc + ix] * sly[s * Pc + iy];
        reds_add_f32(img_u32 + 4u * (unsigned)(base + loff), v);
    }
    {   // batched residuals: pixels (ix=5, iy=2..5) of 8 spots, one atomic
        const int s2   = w * 8 + (lane >> 2);
        const int iy2  = 2 + (lane & 3);
        const float v  = slx[s2 * Pc + 5] * sly[s2 * Pc + iy2];
        reds_add_f32(img_u32 + 4u * (unsigned)(sbase[s2] + RS * 5 + iy2), v);  // base+350+iy2
    }
    __syncthreads();

    // ---- phase D: batch 8 LDS.64 (MLP), then 8 coalesced STG.64 ----
    float2 v[8];
    #pragma unroll
    for (int k = 0; k < 8; k++) {
        const int i  = k * TPB + tid;            // float2 cell 0..2047
        const int r  = i >> 5;                   // warp-uniform
        const int c2 = i & 31;
        v[k] = *reinterpret_cast<const float2*>(&img[RS * r + 2 * c2]);
    }
    float2* o2 = reinterpret_cast<float2*>(out + (size_t)b * (NXc * NYc));
    #pragma unroll
    for (int k = 0; k < 8; k++)
        o2[k * TPB + tid] = v[k];
}

extern "C" void kernel_launch(void* const* d_in, const int* in_sizes, int n_in,
                              void* d_out, int out_size)
{
    const float* z = (const float*)d_in[0];
    float* out = (float*)d_out;
    const int B = in_sizes[0] / (2 * NSPOTS);   // 8192
    spot_render_kernel<<<B, TPB>>>(z, out);
}